// round 1
// baseline (speedup 1.0000x reference)
#include <cuda_runtime.h>

#define BB 2
#define LL 2048
#define DD 1024
#define HH 16
#define DKK 64
#define M_ROWS (BB*LL)      // 4096
#define QKV_N (3*DD)        // 3072

// Scratch (device globals: allocation-free per harness rules)
__device__ float g_qkv[(size_t)M_ROWS * QKV_N];   // 48 MB
__device__ float g_attn[(size_t)M_ROWS * DD];     // 16 MB

// ---------------------------------------------------------------------------
// SGEMM + bias: C[M,N] = A[M,K] @ B[K,N] + bias[N]
// 128x128 block tile, BK=16, 256 threads, 8x8 microtile (4+4 split fragments)
// ---------------------------------------------------------------------------
__global__ __launch_bounds__(256) void sgemm_bias_kernel(
    const float* __restrict__ A, const float* __restrict__ Bm,
    const float* __restrict__ bias, float* __restrict__ C,
    int M, int N, int K)
{
    __shared__ float As[16][128];   // transposed A tile: As[k][m]
    __shared__ float Bs[16][128];   // Bs[k][n]

    const int tid = threadIdx.x;
    const int tx = tid & 15, ty = tid >> 4;
    const int rowBase = blockIdx.y * 128;
    const int colBase = blockIdx.x * 128;

    float acc[8][8];
    #pragma unroll
    for (int i = 0; i < 8; i++)
        #pragma unroll
        for (int j = 0; j < 8; j++) acc[i][j] = 0.f;

    for (int k0 = 0; k0 < K; k0 += 16) {
        // Load A tile 128x16 (transpose into As[k][m])
        #pragma unroll
        for (int i = 0; i < 2; i++) {
            int f = tid + i * 256;          // float4 index 0..511
            int r = f >> 2;                 // 0..127
            int kb = (f & 3) << 2;          // 0,4,8,12
            float4 a = *(const float4*)(A + (size_t)(rowBase + r) * K + k0 + kb);
            As[kb + 0][r] = a.x; As[kb + 1][r] = a.y;
            As[kb + 2][r] = a.z; As[kb + 3][r] = a.w;
        }
        // Load B tile 16x128
        #pragma unroll
        for (int i = 0; i < 2; i++) {
            int f = tid + i * 256;
            int r = f >> 5;                 // 0..15
            int c = (f & 31) << 2;          // 0..124
            *(float4*)&Bs[r][c] = *(const float4*)(Bm + (size_t)(k0 + r) * N + colBase + c);
        }
        __syncthreads();

        #pragma unroll
        for (int kk = 0; kk < 16; kk++) {
            float a[8], b[8];
            *(float4*)&a[0] = *(float4*)&As[kk][ty * 4];
            *(float4*)&a[4] = *(float4*)&As[kk][64 + ty * 4];
            *(float4*)&b[0] = *(float4*)&Bs[kk][tx * 4];
            *(float4*)&b[4] = *(float4*)&Bs[kk][64 + tx * 4];
            #pragma unroll
            for (int i = 0; i < 8; i++)
                #pragma unroll
                for (int j = 0; j < 8; j++)
                    acc[i][j] = fmaf(a[i], b[j], acc[i][j]);
        }
        __syncthreads();
    }

    // Epilogue: + bias, write out (split 4+4 mapping)
    #pragma unroll
    for (int i = 0; i < 8; i++) {
        int r = rowBase + ((i < 4) ? (ty * 4 + i) : (64 + ty * 4 + i - 4));
        #pragma unroll
        for (int jj = 0; jj < 2; jj++) {
            int c = colBase + ((jj == 0) ? (tx * 4) : (64 + tx * 4));
            float4 v;
            v.x = acc[i][jj * 4 + 0] + bias[c + 0];
            v.y = acc[i][jj * 4 + 1] + bias[c + 1];
            v.z = acc[i][jj * 4 + 2] + bias[c + 2];
            v.w = acc[i][jj * 4 + 3] + bias[c + 3];
            *(float4*)(C + (size_t)r * N + c) = v;
        }
    }
}

// ---------------------------------------------------------------------------
// Flash attention (fp32, online softmax).
// Grid: (L/32, B*H). Block: 256 threads = 16x16.
// Q tile 32 rows, KV tile 64 rows. Thread (ty,tx) owns:
//   S rows r0=2*ty..+1, S cols (keys) {tx+16j, j=0..3}
//   O rows same, O cols (dk) c0=4*tx..+3
// K tile stride 68 (16B-aligned rows, banks spread); P reuses K buffer.
// ---------------------------------------------------------------------------
__global__ __launch_bounds__(256) void attention_kernel(
    const float* __restrict__ qkv, float* __restrict__ attn_out)
{
    __shared__ float Qs[32 * 64];
    __shared__ float Ks[64 * 68];   // K tile; reused for P (32 rows, stride 68)
    __shared__ float Vs[64 * 64];

    const int tid = threadIdx.x;
    const int tx = tid & 15, ty = tid >> 4;
    const int bh = blockIdx.y;
    const int b = bh >> 4, h = bh & 15;
    const int q0 = blockIdx.x * 32;
    const float* base = qkv + (size_t)b * LL * QKV_N + h * (3 * DKK);

    // Load Q tile 32x64
    #pragma unroll
    for (int i = 0; i < 2; i++) {
        int f = tid + i * 256;
        int r = f >> 4;
        int c = (f & 15) << 2;
        *(float4*)&Qs[r * 64 + c] = *(const float4*)(base + (size_t)(q0 + r) * QKV_N + c);
    }

    const int r0 = ty * 2;
    const int c0 = tx * 4;
    float m[2] = {-1e30f, -1e30f};
    float l[2] = {0.f, 0.f};
    float o[2][4];
    #pragma unroll
    for (int i = 0; i < 2; i++)
        #pragma unroll
        for (int j = 0; j < 4; j++) o[i][j] = 0.f;

    const float scale = 0.125f;  // 1/sqrt(64)

    for (int k0 = 0; k0 < LL; k0 += 64) {
        // Load K and V tiles (64x64 each)
        #pragma unroll
        for (int i = 0; i < 4; i++) {
            int f = tid + i * 256;
            int r = f >> 4;
            int c = (f & 15) << 2;
            const float* gk = base + (size_t)(k0 + r) * QKV_N;
            *(float4*)&Ks[r * 68 + c] = *(const float4*)(gk + DKK + c);
            *(float4*)&Vs[r * 64 + c] = *(const float4*)(gk + 2 * DKK + c);
        }
        __syncthreads();

        // S = Q @ K^T (keys for this thread: tx + 16*j)
        float s[2][4];
        #pragma unroll
        for (int i = 0; i < 2; i++)
            #pragma unroll
            for (int j = 0; j < 4; j++) s[i][j] = 0.f;

        #pragma unroll
        for (int kk = 0; kk < 64; kk += 4) {
            float4 qa = *(float4*)&Qs[r0 * 64 + kk];
            float4 qb = *(float4*)&Qs[(r0 + 1) * 64 + kk];
            #pragma unroll
            for (int j = 0; j < 4; j++) {
                float4 kv = *(float4*)&Ks[(tx + 16 * j) * 68 + kk];
                s[0][j] = fmaf(qa.x, kv.x, s[0][j]);
                s[0][j] = fmaf(qa.y, kv.y, s[0][j]);
                s[0][j] = fmaf(qa.z, kv.z, s[0][j]);
                s[0][j] = fmaf(qa.w, kv.w, s[0][j]);
                s[1][j] = fmaf(qb.x, kv.x, s[1][j]);
                s[1][j] = fmaf(qb.y, kv.y, s[1][j]);
                s[1][j] = fmaf(qb.z, kv.z, s[1][j]);
                s[1][j] = fmaf(qb.w, kv.w, s[1][j]);
            }
        }

        // Online softmax update (reduction across 16 lanes sharing rows)
        #pragma unroll
        for (int i = 0; i < 2; i++) {
            #pragma unroll
            for (int j = 0; j < 4; j++) s[i][j] *= scale;
            float rm = fmaxf(fmaxf(s[i][0], s[i][1]), fmaxf(s[i][2], s[i][3]));
            #pragma unroll
            for (int off = 8; off >= 1; off >>= 1)
                rm = fmaxf(rm, __shfl_xor_sync(0xffffffffu, rm, off));
            float mn = fmaxf(m[i], rm);
            float alpha = __expf(m[i] - mn);
            float rs = 0.f;
            #pragma unroll
            for (int j = 0; j < 4; j++) {
                s[i][j] = __expf(s[i][j] - mn);
                rs += s[i][j];
            }
            #pragma unroll
            for (int off = 8; off >= 1; off >>= 1)
                rs += __shfl_xor_sync(0xffffffffu, rs, off);
            l[i] = l[i] * alpha + rs;
            m[i] = mn;
            #pragma unroll
            for (int j = 0; j < 4; j++) o[i][j] *= alpha;
        }
        __syncthreads();   // all K-tile reads done before overwriting as P

        // Store P into Ks buffer (P[row][key], stride 68)
        #pragma unroll
        for (int i = 0; i < 2; i++)
            #pragma unroll
            for (int j = 0; j < 4; j++)
                Ks[(r0 + i) * 68 + tx + 16 * j] = s[i][j];
        __syncthreads();

        // O += P @ V
        #pragma unroll 8
        for (int kk = 0; kk < 64; kk++) {
            float p0 = Ks[r0 * 68 + kk];
            float p1 = Ks[(r0 + 1) * 68 + kk];
            float4 vv = *(float4*)&Vs[kk * 64 + c0];
            o[0][0] = fmaf(p0, vv.x, o[0][0]);
            o[0][1] = fmaf(p0, vv.y, o[0][1]);
            o[0][2] = fmaf(p0, vv.z, o[0][2]);
            o[0][3] = fmaf(p0, vv.w, o[0][3]);
            o[1][0] = fmaf(p1, vv.x, o[1][0]);
            o[1][1] = fmaf(p1, vv.y, o[1][1]);
            o[1][2] = fmaf(p1, vv.z, o[1][2]);
            o[1][3] = fmaf(p1, vv.w, o[1][3]);
        }
        __syncthreads();
    }

    // Normalize and write [B, L, H*DK]
    #pragma unroll
    for (int i = 0; i < 2; i++) {
        float inv = 1.f / l[i];
        float4 v = make_float4(o[i][0] * inv, o[i][1] * inv, o[i][2] * inv, o[i][3] * inv);
        *(float4*)(attn_out + (size_t)(b * LL + q0 + r0 + i) * DD + h * DKK + c0) = v;
    }
}

// ---------------------------------------------------------------------------
extern "C" void kernel_launch(void* const* d_in, const int* in_sizes, int n_in,
                              void* d_out, int out_size)
{
    const float* x     = (const float*)d_in[0];   // [2,2048,1024]
    const float* w_qkv = (const float*)d_in[1];   // [1024,3072]
    const float* b_qkv = (const float*)d_in[2];   // [3072]
    const float* w_out = (const float*)d_in[3];   // [1024,1024]
    const float* b_out = (const float*)d_in[4];   // [1024]
    float* out = (float*)d_out;                   // [2,2048,1024]

    float *qkv_ptr = nullptr, *attn_ptr = nullptr;
    cudaGetSymbolAddress((void**)&qkv_ptr, g_qkv);
    cudaGetSymbolAddress((void**)&attn_ptr, g_attn);

    // 1) QKV projection: [4096,1024] @ [1024,3072] + b_qkv
    dim3 g1(QKV_N / 128, M_ROWS / 128);
    sgemm_bias_kernel<<<g1, 256>>>(x, w_qkv, b_qkv, qkv_ptr, M_ROWS, QKV_N, DD);

    // 2) Flash attention
    dim3 g2(LL / 32, BB * HH);
    attention_kernel<<<g2, 256>>>(qkv_ptr, attn_ptr);

    // 3) Output projection: [4096,1024] @ [1024,1024] + b_out
    dim3 g3(DD / 128, M_ROWS / 128);
    sgemm_bias_kernel<<<g3, 256>>>(attn_ptr, w_out, b_out, out, M_ROWS, DD, DD);
}

// round 4
// speedup vs baseline: 1.4653x; 1.4653x over previous
#include <cuda_runtime.h>
#include <cstdint>

#define BB 2
#define LL 2048
#define DD 1024
#define HH 16
#define DKK 64
#define M_ROWS (BB*LL)      // 4096
#define QKV_N (3*DD)        // 3072

// Scratch (device globals: allocation-free per harness rules)
__device__ float g_qkv[(size_t)M_ROWS * QKV_N];   // 48 MB
__device__ float g_attn[(size_t)M_ROWS * DD];     // 16 MB

// ---------------------------------------------------------------------------
// cp.async helpers (LDGSTS)
// ---------------------------------------------------------------------------
__device__ __forceinline__ void cp_async16(void* smem_dst, const void* gptr) {
    uint32_t s = (uint32_t)__cvta_generic_to_shared(smem_dst);
    asm volatile("cp.async.cg.shared.global [%0], [%1], 16;\n" :: "r"(s), "l"(gptr));
}
__device__ __forceinline__ void cp_commit() {
    asm volatile("cp.async.commit_group;\n");
}
template<int N>
__device__ __forceinline__ void cp_wait() {
    asm volatile("cp.async.wait_group %0;\n" :: "n"(N));
}

// ---------------------------------------------------------------------------
// SGEMM + bias: C[M,N] = A[M,K] @ B[K,N] + bias[N]
// 128x128 tile, BK=16, 256 threads, 8x8 microtile.
// Double-buffered smem with cp.async prefetch (no register staging).
// A stored untransposed [m][k]; A-fragment = broadcast scalar LDS.
// ---------------------------------------------------------------------------
__global__ __launch_bounds__(256) void sgemm_bias_kernel(
    const float* __restrict__ A, const float* __restrict__ Bm,
    const float* __restrict__ bias, float* __restrict__ C,
    int M, int N, int K)
{
    __shared__ __align__(16) float As[2][128 * 16];   // [m][k]
    __shared__ __align__(16) float Bs[2][16 * 128];   // [k][n]

    const int tid = threadIdx.x;
    const int tx = tid & 15, ty = tid >> 4;
    const int rowBase = blockIdx.y * 128;
    const int colBase = blockIdx.x * 128;

    const int T = K >> 4;

    // Prologue: prefetch tile 0 into buffer 0
    #pragma unroll
    for (int i = 0; i < 2; i++) {
        int f = tid + (i << 8);
        int r = f >> 2, kb = (f & 3) << 2;
        cp_async16(&As[0][r * 16 + kb], A + (size_t)(rowBase + r) * K + kb);
        int rb = f >> 5, cb = (f & 31) << 2;
        cp_async16(&Bs[0][rb * 128 + cb], Bm + (size_t)rb * N + colBase + cb);
    }
    cp_commit();

    float acc[8][8];
    #pragma unroll
    for (int i = 0; i < 8; i++)
        #pragma unroll
        for (int j = 0; j < 8; j++) acc[i][j] = 0.f;

    for (int t = 0; t < T; t++) {
        const int cur = t & 1;
        if (t + 1 < T) {
            const int nb = cur ^ 1;
            const int k0 = (t + 1) << 4;
            #pragma unroll
            for (int i = 0; i < 2; i++) {
                int f = tid + (i << 8);
                int r = f >> 2, kb = (f & 3) << 2;
                cp_async16(&As[nb][r * 16 + kb], A + (size_t)(rowBase + r) * K + k0 + kb);
                int rb = f >> 5, cb = (f & 31) << 2;
                cp_async16(&Bs[nb][rb * 128 + cb], Bm + (size_t)(k0 + rb) * N + colBase + cb);
            }
            cp_commit();
            cp_wait<1>();   // tile t complete; tile t+1 may stay in flight
        } else {
            cp_wait<0>();
        }
        __syncthreads();

        const float* Ac = As[cur];
        const float* Bc = Bs[cur];
        #pragma unroll
        for (int kk = 0; kk < 16; kk++) {
            float a[8], b[8];
            #pragma unroll
            for (int i = 0; i < 4; i++) {
                a[i]     = Ac[(ty * 4 + i) * 16 + kk];
                a[4 + i] = Ac[(64 + ty * 4 + i) * 16 + kk];
            }
            *(float4*)&b[0] = *(const float4*)&Bc[kk * 128 + tx * 4];
            *(float4*)&b[4] = *(const float4*)&Bc[kk * 128 + 64 + tx * 4];
            #pragma unroll
            for (int i = 0; i < 8; i++)
                #pragma unroll
                for (int j = 0; j < 8; j++)
                    acc[i][j] = fmaf(a[i], b[j], acc[i][j]);
        }
        __syncthreads();   // reads of buffer `cur` done before it is refilled
    }

    // Epilogue: + bias
    #pragma unroll
    for (int i = 0; i < 8; i++) {
        int r = rowBase + ((i < 4) ? (ty * 4 + i) : (64 + ty * 4 + i - 4));
        #pragma unroll
        for (int jj = 0; jj < 2; jj++) {
            int c = colBase + ((jj == 0) ? (tx * 4) : (64 + tx * 4));
            float4 v;
            v.x = acc[i][jj * 4 + 0] + bias[c + 0];
            v.y = acc[i][jj * 4 + 1] + bias[c + 1];
            v.z = acc[i][jj * 4 + 2] + bias[c + 2];
            v.w = acc[i][jj * 4 + 3] + bias[c + 3];
            *(float4*)(C + (size_t)r * N + c) = v;
        }
    }
}

// ---------------------------------------------------------------------------
// Flash attention (fp32, online softmax).
// Grid: (L/64, B*H). Block: 256 threads = 16(tx) x 16(ty).
// Q tile 64, KV tile 64. Thread (ty,tx) owns S/O microtile 4x4:
//   rows r0=4*ty..+3, S cols (keys) c0=4*tx..+3, O cols (dk) c0..+3.
// K tile XOR-swizzled per 16B chunk: chunk kc of row r lives at kc ^ (r&15)
// -> key-fragment LDS.128 is conflict-free. P reuses the K buffer (plain).
// Q pre-scaled by 1/sqrt(dk) at load.
// ---------------------------------------------------------------------------
__global__ __launch_bounds__(256) void attention_kernel(
    const float* __restrict__ qkv, float* __restrict__ attn_out)
{
    __shared__ __align__(16) float Qs[64 * 64];
    __shared__ __align__(16) float Ks[64 * 64];   // swizzled K; reused as P
    __shared__ __align__(16) float Vs[64 * 64];

    const int tid = threadIdx.x;
    const int tx = tid & 15, ty = tid >> 4;
    const int b = blockIdx.y >> 4, h = blockIdx.y & 15;
    const int q0 = blockIdx.x * 64;
    const float* base = qkv + (size_t)b * LL * QKV_N + h * (3 * DKK);

    const float scale = 0.125f;  // 1/sqrt(64)

    // Load Q tile 64x64, pre-scaled
    #pragma unroll
    for (int i = 0; i < 4; i++) {
        int f = tid + (i << 8);
        int r = f >> 4, c = (f & 15) << 2;
        float4 v = *(const float4*)(base + (size_t)(q0 + r) * QKV_N + c);
        v.x *= scale; v.y *= scale; v.z *= scale; v.w *= scale;
        *(float4*)&Qs[r * 64 + c] = v;
    }

    const int r0 = ty << 2, c0 = tx << 2;
    float m[4] = {-1e30f, -1e30f, -1e30f, -1e30f};
    float l[4] = {0.f, 0.f, 0.f, 0.f};
    float o[4][4];
    #pragma unroll
    for (int i = 0; i < 4; i++)
        #pragma unroll
        for (int j = 0; j < 4; j++) o[i][j] = 0.f;

    for (int k0 = 0; k0 < LL; k0 += 64) {
        __syncthreads();   // prior PV reads of Ks(P)/Vs done before refill

        // Load K (swizzled) and V (plain) tiles, 64x64 each
        #pragma unroll
        for (int i = 0; i < 4; i++) {
            int f = tid + (i << 8);
            int r = f >> 4, cc = f & 15;
            const float* gk = base + (size_t)(k0 + r) * QKV_N;
            *(float4*)&Ks[r * 64 + ((cc ^ (r & 15)) << 2)] = *(const float4*)(gk + DKK + (cc << 2));
            *(float4*)&Vs[r * 64 + (cc << 2)]              = *(const float4*)(gk + 2 * DKK + (cc << 2));
        }
        __syncthreads();

        // S = Q @ K^T  (4x4 microtile)
        float s[4][4];
        #pragma unroll
        for (int i = 0; i < 4; i++)
            #pragma unroll
            for (int j = 0; j < 4; j++) s[i][j] = 0.f;

        #pragma unroll 4
        for (int kc = 0; kc < 16; kc++) {
            float4 q[4], kf[4];
            #pragma unroll
            for (int i = 0; i < 4; i++)
                q[i] = *(const float4*)&Qs[(r0 + i) * 64 + (kc << 2)];
            #pragma unroll
            for (int j = 0; j < 4; j++) {
                int c = c0 + j;
                kf[j] = *(const float4*)&Ks[c * 64 + ((kc ^ (c & 15)) << 2)];
            }
            #pragma unroll
            for (int i = 0; i < 4; i++)
                #pragma unroll
                for (int j = 0; j < 4; j++) {
                    s[i][j] = fmaf(q[i].x, kf[j].x, s[i][j]);
                    s[i][j] = fmaf(q[i].y, kf[j].y, s[i][j]);
                    s[i][j] = fmaf(q[i].z, kf[j].z, s[i][j]);
                    s[i][j] = fmaf(q[i].w, kf[j].w, s[i][j]);
                }
        }

        // Online softmax (row reduction across the 16 tx lanes)
        #pragma unroll
        for (int i = 0; i < 4; i++) {
            float rm = fmaxf(fmaxf(s[i][0], s[i][1]), fmaxf(s[i][2], s[i][3]));
            #pragma unroll
            for (int off = 8; off >= 1; off >>= 1)
                rm = fmaxf(rm, __shfl_xor_sync(0xffffffffu, rm, off));
            float mn = fmaxf(m[i], rm);
            float alpha = __expf(m[i] - mn);
            float rs = 0.f;
            #pragma unroll
            for (int j = 0; j < 4; j++) {
                s[i][j] = __expf(s[i][j] - mn);
                rs += s[i][j];
            }
            #pragma unroll
            for (int off = 8; off >= 1; off >>= 1)
                rs += __shfl_xor_sync(0xffffffffu, rs, off);
            l[i] = l[i] * alpha + rs;
            m[i] = mn;
            #pragma unroll
            for (int j = 0; j < 4; j++) o[i][j] *= alpha;
        }
        __syncthreads();   // all K-tile reads done before overwrite as P

        // Store P into Ks buffer (plain stride 64)
        #pragma unroll
        for (int i = 0; i < 4; i++)
            *(float4*)&Ks[(r0 + i) * 64 + c0] =
                make_float4(s[i][0], s[i][1], s[i][2], s[i][3]);
        __syncthreads();

        // O += P @ V
        #pragma unroll 8
        for (int kk = 0; kk < 64; kk++) {
            float4 vv = *(const float4*)&Vs[kk * 64 + c0];
            float p0 = Ks[(r0 + 0) * 64 + kk];
            float p1 = Ks[(r0 + 1) * 64 + kk];
            float p2 = Ks[(r0 + 2) * 64 + kk];
            float p3 = Ks[(r0 + 3) * 64 + kk];
            o[0][0] = fmaf(p0, vv.x, o[0][0]); o[0][1] = fmaf(p0, vv.y, o[0][1]);
            o[0][2] = fmaf(p0, vv.z, o[0][2]); o[0][3] = fmaf(p0, vv.w, o[0][3]);
            o[1][0] = fmaf(p1, vv.x, o[1][0]); o[1][1] = fmaf(p1, vv.y, o[1][1]);
            o[1][2] = fmaf(p1, vv.z, o[1][2]); o[1][3] = fmaf(p1, vv.w, o[1][3]);
            o[2][0] = fmaf(p2, vv.x, o[2][0]); o[2][1] = fmaf(p2, vv.y, o[2][1]);
            o[2][2] = fmaf(p2, vv.z, o[2][2]); o[2][3] = fmaf(p2, vv.w, o[2][3]);
            o[3][0] = fmaf(p3, vv.x, o[3][0]); o[3][1] = fmaf(p3, vv.y, o[3][1]);
            o[3][2] = fmaf(p3, vv.z, o[3][2]); o[3][3] = fmaf(p3, vv.w, o[3][3]);
        }
    }

    // Normalize and write [B, L, H*DK]
    #pragma unroll
    for (int i = 0; i < 4; i++) {
        float inv = 1.f / l[i];
        float4 v = make_float4(o[i][0] * inv, o[i][1] * inv,
                               o[i][2] * inv, o[i][3] * inv);
        *(float4*)(attn_out + (size_t)(b * LL + q0 + r0 + i) * DD + h * DKK + c0) = v;
    }
}

// ---------------------------------------------------------------------------
extern "C" void kernel_launch(void* const* d_in, const int* in_sizes, int n_in,
                              void* d_out, int out_size)
{
    const float* x     = (const float*)d_in[0];   // [2,2048,1024]
    const float* w_qkv = (const float*)d_in[1];   // [1024,3072]
    const float* b_qkv = (const float*)d_in[2];   // [3072]
    const float* w_out = (const float*)d_in[3];   // [1024,1024]
    const float* b_out = (const float*)d_in[4];   // [1024]
    float* out = (float*)d_out;                   // [2,2048,1024]

    float *qkv_ptr = nullptr, *attn_ptr = nullptr;
    cudaGetSymbolAddress((void**)&qkv_ptr, g_qkv);
    cudaGetSymbolAddress((void**)&attn_ptr, g_attn);

    // 1) QKV projection: [4096,1024] @ [1024,3072] + b_qkv
    dim3 g1(QKV_N / 128, M_ROWS / 128);
    sgemm_bias_kernel<<<g1, 256>>>(x, w_qkv, b_qkv, qkv_ptr, M_ROWS, QKV_N, DD);

    // 2) Flash attention
    dim3 g2(LL / 64, BB * HH);
    attention_kernel<<<g2, 256>>>(qkv_ptr, attn_ptr);

    // 3) Output projection: [4096,1024] @ [1024,1024] + b_out
    dim3 g3(DD / 128, M_ROWS / 128);
    sgemm_bias_kernel<<<g3, 256>>>(attn_ptr, w_out, b_out, out, M_ROWS, DD, DD);
}